// round 17
// baseline (speedup 1.0000x reference)
#include <cuda_runtime.h>
#include <cstdint>
#include <type_traits>

namespace {

constexpr int LD  = 9;     // 2*lambd+1
constexpr int NP  = 61;    // valid (mu,m1) / (mup,m1p) pairs
constexpr int BLK = 32;    // samples per tile
constexpr int THR = 64;    // 2 threads per sample (mup column split)
constexpr int T4  = BLK * 81 / 4;  // 648 float4 per tile matrix

// Balanced output-column split: FFMA 1891 vs 1830, acc 45 vs 36.
constexpr int MASK0 = 0b100001111;  // mup {0,1,2,3,8}
constexpr int MASK1 = 0b011110000;  // mup {4,5,6,7}

__host__ __device__ constexpr int imax(int a, int b) { return a > b ? a : b; }
__host__ __device__ constexpr int imin(int a, int b) { return a < b ? a : b; }

__host__ __device__ constexpr int lo_m(int m2) { return imax(0, 4 - m2); }
__host__ __device__ constexpr int hi_m(int m2) { return imin(8, 12 - m2); }

__host__ __device__ constexpr int cntmu(int mu) { return 9 - (mu >= 4 ? mu - 4 : 4 - mu); }
__host__ __device__ constexpr int ofsmu(int mu) {
    int o = 0;
    for (int i = 0; i < mu; i++) o += cntmu(i);
    return o;
}
// pair index for (m1,m2): mu-major, m1 ascending (matches reference enumeration)
__host__ __device__ constexpr int pidx(int m1, int m2) {
    int mu   = m1 + m2 - 4;
    int m1lo = imax(0, mu - 4);
    return ofsmu(mu) + (m1 - m1lo);
}

__host__ __device__ constexpr bool inmask(int mask, int mup) { return (mask >> mup) & 1; }
__host__ __device__ constexpr int nmup(int mask) {
    int c = 0;
    for (int i = 0; i < 9; i++) c += (mask >> i) & 1;
    return c;
}
__host__ __device__ constexpr int lmup(int mask, int mup) {
    int c = 0;
    for (int i = 0; i < mup; i++) c += (mask >> i) & 1;
    return c;
}
// role-local g layout: q's (ordered by m2p, m1p) whose mup is in mask
__host__ __device__ constexpr int gsize(int mask) {
    int c = 0;
    for (int m2p = 0; m2p < 9; m2p++)
        for (int m1p = lo_m(m2p); m1p <= hi_m(m2p); m1p++)
            if (inmask(mask, m1p + m2p - 4)) c++;
    return c;
}
__host__ __device__ constexpr int gidx(int mask, int M2P, int M1P) {
    int c = 0;
    for (int m2p = 0; m2p < 9; m2p++)
        for (int m1p = lo_m(m2p); m1p <= hi_m(m2p); m1p++) {
            if (m2p == M2P && m1p == M1P) return c;
            if (inmask(mask, m1p + m2p - 4)) c++;
        }
    return -1;
}

template <int S, int E, class F>
__device__ __forceinline__ void static_for(F&& f) {
    if constexpr (S < E) {
        f(std::integral_constant<int, S>{});
        static_for<S + 1, E>(f);
    }
}

__device__ __forceinline__ uint32_t smem_u32(const void* p) {
    uint32_t a;
    asm("{ .reg .u64 t; cvta.to.shared.u64 t, %1; cvt.u32.u64 %0, t; }" : "=r"(a) : "l"(p));
    return a;
}
// 16B async copy, src_size 0 -> zero-fill (branch-free tail handling)
__device__ __forceinline__ void cp16(uint32_t dst, const float4* src, int sz) {
    asm volatile("cp.async.cg.shared.global [%0], [%1], 16, %2;\n"
                 :: "r"(dst), "l"(src), "r"(sz));
}
// Issue one tile matrix (648 float4) from gsrc tile `tile` into smem buffer.
__device__ __forceinline__ void issue_tile(uint32_t dsmem, const float* gsrc,
                                           int tile, int tot4, int tid) {
    const int     gbase4 = tile * T4;
    const float4* s      = reinterpret_cast<const float4*>(gsrc);
#pragma unroll
    for (int k = 0; k < (T4 + THR - 1) / THR; k++) {
        const int idx = k * THR + tid;
        if (idx < T4) {
            const int sz = (gbase4 + idx < tot4) ? 16 : 0;
            cp16(dsmem + idx * 16, s + gbase4 + idx, sz);
        }
    }
}

// R16 compute body: this sample's output columns (mup in MASK) for all mu.
// X1 register-resident, x2 row in registers, full role g, t pure FMUL.
template <int MASK>
__device__ __forceinline__ void compute_role(const float (&x1r)[81],
                                             const float* __restrict__ x2t,
                                             const float* __restrict__ us,
                                             const float* __restrict__ vs,
                                             float (&acc)[45]) {
    constexpr int NM = nmup(MASK);
    constexpr int GN = gsize(MASK);

#pragma unroll
    for (int i = 0; i < 9 * NM; i++) acc[i] = 0.0f;

    static_for<0, LD>([&](auto M2c) {
        constexpr int m2 = decltype(M2c)::value;

        float x2r[LD];
        static_for<0, LD>([&](auto Jc) {
            constexpr int j = decltype(Jc)::value;
            x2r[j] = x2t[m2 * LD + j];                 // conflict-free LDS
        });

        float g[GN];
        static_for<0, LD>([&](auto Jc) {
            constexpr int m2p = decltype(Jc)::value;
            static_for<lo_m(m2p), hi_m(m2p) + 1>([&](auto Ic) {
                constexpr int m1p = decltype(Ic)::value;
                if constexpr (inmask(MASK, m1p + m2p - 4))
                    g[gidx(MASK, m2p, m1p)] = vs[pidx(m1p, m2p)] * x2r[m2p];
            });
        });

        static_for<lo_m(m2), hi_m(m2) + 1>([&](auto Mc) {
            constexpr int m1 = decltype(Mc)::value;
            const float uu = us[pidx(m1, m2)];
            float t[LD];
            static_for<0, LD>([&](auto Kc) {
                constexpr int k = decltype(Kc)::value;
                t[k] = uu * x1r[m1 * LD + k];          // register source, no LDS
            });
            static_for<0, LD>([&](auto Jc) {
                constexpr int m2p = decltype(Jc)::value;
                static_for<lo_m(m2p), hi_m(m2p) + 1>([&](auto Ic) {
                    constexpr int m1p = decltype(Ic)::value;
                    if constexpr (inmask(MASK, m1p + m2p - 4)) {
                        constexpr int mup = m1p + m2p - 4;
                        acc[(m1 + m2 - 4) * NM + lmup(MASK, mup)] +=
                            t[m1p] * g[gidx(MASK, m2p, m1p)];
                    }
                });
            });
        });
    });
}

template <int MASK>
__device__ __forceinline__ void store_role(const float (&acc)[45],
                                           float* __restrict__ stage) {
    constexpr int NM = nmup(MASK);
    static_for<0, LD>([&](auto Mc) {
        constexpr int mu = decltype(Mc)::value;
        static_for<0, LD>([&](auto Pc) {
            constexpr int mup = decltype(Pc)::value;
            if constexpr (inmask(MASK, mup))
                stage[mu * LD + mup] = acc[mu * NM + lmup(MASK, mup)];
        });
    });
}

__global__ void __launch_bounds__(THR, 6)   // <=170 regs -> 6 blocks = 12 warps/SM
wigner_kernel(const float* __restrict__ X1,
              const float* __restrict__ X2,
              const float* __restrict__ mult,
              float* __restrict__ out, int n) {
    // 3 tile buffers (31 KB): x1 single (extracted to regs early, then reused
    // for tile1's x1), x2 double-buffered. 6 blocks/SM preserved.
    __shared__ __align__(16) float x1s[BLK * 81];
    __shared__ __align__(16) float x2a[BLK * 81];
    __shared__ __align__(16) float x2b[BLK * 81];
    __shared__ float us[NP];
    __shared__ float vs[NP];

    const int  tid    = threadIdx.x;
    const int  lane   = tid & (BLK - 1);   // sample within tile
    const int  role   = tid >> 5;          // warp 0: MASK0, warp 1: MASK1
    const int  ntiles = (n + BLK - 1) / BLK;
    const int  t0     = 2 * blockIdx.x;
    const bool has1   = (t0 + 1) < ntiles;  // block-uniform
    const int  tot4   = n * 81 / 4;

    const uint32_t d1 = smem_u32(x1s);
    const uint32_t da = smem_u32(x2a);
    const uint32_t db = smem_u32(x2b);

    // Rank-1 refactorization of mult: mult[p*61+q] = c[p]*c[q]
    if (tid < NP) {
        vs[tid] = mult[tid];
        us[tid] = mult[tid * NP] * (1.0f / mult[0]);
    }

    // G0: tile0 (x1 + x2a).  G1: prefetch tile1 x2 -> x2b (hidden behind tile0).
    issue_tile(d1, X1, t0, tot4, tid);
    issue_tile(da, X2, t0, tot4, tid);
    asm volatile("cp.async.commit_group;\n");
    if (has1) issue_tile(db, X2, t0 + 1, tot4, tid);
    asm volatile("cp.async.commit_group;\n");

#pragma unroll 1
    for (int it = 0; it < 2; ++it) {
        if (it == 1 && !has1) break;          // block-uniform exit
        const int tile = t0 + it;
        float* x2cur = it ? x2b : x2a;

        if (it == 0) { asm volatile("cp.async.wait_group 1;\n" ::: "memory"); }
        else         { asm volatile("cp.async.wait_group 0;\n" ::: "memory"); }
        __syncthreads();                       // tile data visible block-wide

        // Pull X1 into registers (81 conflict-free LDS; stride 81 is odd).
        float x1r[81];
        {
            const float* __restrict__ x1t = x1s + lane * 81;
            static_for<0, 81>([&](auto Ic) {
                constexpr int i = decltype(Ic)::value;
                x1r[i] = x1t[i];
            });
        }
        __syncthreads();                       // x1s free for reuse

        // G2: tile1's x1 loads entirely behind tile0 compute.
        if (it == 0 && has1) issue_tile(d1, X1, t0 + 1, tot4, tid);
        asm volatile("cp.async.commit_group;\n");

        float acc[45];
        {
            const float* __restrict__ x2t = x2cur + lane * 81;
            if (role == 0) compute_role<MASK0>(x1r, x2t, us, vs, acc);
            else           compute_role<MASK1>(x1r, x2t, us, vs, acc);
        }
        __syncthreads();                       // all x2cur reads done
        {
            float* stage = x2cur + lane * 81;  // role partners: disjoint columns
            if (role == 0) store_role<MASK0>(acc, stage);
            else           store_role<MASK1>(acc, stage);
        }
        __syncthreads();                       // staging visible

        // Coalesced float4 writeback of this tile.
        {
            const float4* srcs   = reinterpret_cast<const float4*>(x2cur);
            float4*       dsto   = reinterpret_cast<float4*>(out);
            const int     gbase4 = tile * T4;
#pragma unroll
            for (int k = 0; k < (T4 + THR - 1) / THR; k++) {
                const int idx = k * THR + tid;
                if (idx < T4 && gbase4 + idx < tot4) dsto[gbase4 + idx] = srcs[idx];
            }
        }
        // No trailing barrier needed: iter1 touches only x1s (guarded by
        // wait_group 0 + sync) and x2b (written before G1 commit).
    }
}

}  // namespace

extern "C" void kernel_launch(void* const* d_in, const int* in_sizes, int n_in,
                              void* d_out, int out_size) {
    const float* X1   = (const float*)d_in[0];
    const float* X2   = (const float*)d_in[1];
    const float* mult = (const float*)d_in[6];
    float*       out  = (float*)d_out;

    const int n      = in_sizes[0] / 81;
    const int ntiles = (n + BLK - 1) / BLK;
    const int blocks = (ntiles + 1) / 2;      // 2 tiles per block
    wigner_kernel<<<blocks, THR>>>(X1, X2, mult, out, n);
}